// round 1
// baseline (speedup 1.0000x reference)
#include <cuda_runtime.h>
#include <math.h>

// ---------------- problem constants ----------------
#define BB 8
#define SS 512
#define DD 1024
#define HH 16
#define DQ 64
#define DV 64
#define DI 4096
#define LL 6
#define NTOK (BB*SS)          // 4096 rows
#define EPSLN 1e-5f

// ---------------- device scratch (no allocations allowed) ----------------
__device__ __align__(16) float g_x  [NTOK*DD];        // 16 MB
__device__ __align__(16) float g_h  [NTOK*DD];        // 16 MB
__device__ __align__(16) float g_q  [NTOK*DD];        // 16 MB
__device__ __align__(16) float g_kv [NTOK*2*DD];      // 32 MB
__device__ __align__(16) float g_o  [NTOK*DD];        // 16 MB
__device__ __align__(16) float g_ffn[NTOK*DI];        // 64 MB
__device__ __align__(16) float g_sc [BB*HH*SS*SS];    // 128 MB
__device__ __align__(16) float g_pe [SS*DD];          // 2 MB

// ---------------- reductions ----------------
__device__ __forceinline__ float warpSum(float v){
#pragma unroll
    for (int o = 16; o; o >>= 1) v += __shfl_xor_sync(0xffffffffu, v, o);
    return v;
}
__device__ __forceinline__ float warpMax(float v){
#pragma unroll
    for (int o = 16; o; o >>= 1) v = fmaxf(v, __shfl_xor_sync(0xffffffffu, v, o));
    return v;
}

// ---------------- positional encoding (double math to match numpy) ----------------
__global__ void pe_kernel(float* __restrict__ pe){
    int idx = blockIdx.x * 256 + threadIdx.x;
    if (idx >= SS*DD) return;
    int s = idx / DD, d = idx % DD;
    double expo  = (double)(2 * (d / 2)) / (double)DD;
    double denom = pow(10000.0, expo);
    double ang   = (double)s / denom;
    pe[idx] = (float)((d % 2 == 0) ? sin(ang) : cos(ang));
}

// ---------------- embedding: x = emb[tok]*sqrt(D) + pe ----------------
__global__ void embed_kernel(const int* __restrict__ tokens,
                             const float* __restrict__ emb,
                             const float* __restrict__ pe,
                             float* __restrict__ x){
    int idx = blockIdx.x * 256 + threadIdx.x;   // over NTOK*DD
    int row = idx / DD, d = idx % DD;
    int s = row % SS;
    int t = tokens[row];
    x[idx] = emb[(long long)t * DD + d] * 32.0f + pe[s * DD + d];
}

// ---------------- layernorm (one block per row of 1024) ----------------
__global__ void ln_kernel(const float* __restrict__ x,
                          const float* __restrict__ g,
                          const float* __restrict__ be,
                          float* __restrict__ y){
    int row = blockIdx.x, tid = threadIdx.x;
    const float4* xr = (const float4*)(x + (long long)row * DD);
    float4 v = xr[tid];
    float s  = v.x + v.y + v.z + v.w;
    float sq = v.x*v.x + v.y*v.y + v.z*v.z + v.w*v.w;
    __shared__ float sh[16];
    s  = warpSum(s);
    sq = warpSum(sq);
    int wid = tid >> 5, lid = tid & 31;
    if (lid == 0){ sh[wid] = s; sh[wid + 8] = sq; }
    __syncthreads();
    if (wid == 0){
        float a  = (lid < 8) ? sh[lid]     : 0.f;
        float b2 = (lid < 8) ? sh[lid + 8] : 0.f;
        a  = warpSum(a);
        b2 = warpSum(b2);
        if (lid == 0){ sh[0] = a; sh[1] = b2; }
    }
    __syncthreads();
    float mean = sh[0] * (1.0f / DD);
    float var  = sh[1] * (1.0f / DD) - mean * mean;
    float rstd = rsqrtf(var + EPSLN);
    float4 gv = ((const float4*)g)[tid];
    float4 bv = ((const float4*)be)[tid];
    float4 o;
    o.x = (v.x - mean) * rstd * gv.x + bv.x;
    o.y = (v.y - mean) * rstd * gv.y + bv.y;
    o.z = (v.z - mean) * rstd * gv.z + bv.z;
    o.w = (v.w - mean) * rstd * gv.w + bv.w;
    ((float4*)(y + (long long)row * DD))[tid] = o;
}

// ---------------- masked softmax over scores rows ----------------
__global__ void softmax_kernel(float* __restrict__ sc, const int* __restrict__ lengths){
    int z = blockIdx.y;            // b*H + h, 0..127
    int q = blockIdx.x;            // 0..511
    int b = z >> 4;
    int len = lengths[b];
    float* row = sc + (((long long)z << 9) + q) * SS;
    int tid = threadIdx.x;
    __shared__ float tmp[SS];
    __shared__ float sh[16];
    float m = -1e30f;
    for (int k = tid; k < len; k += 256){ float v = row[k]; tmp[k] = v; m = fmaxf(m, v); }
    m = warpMax(m);
    int wid = tid >> 5, lid = tid & 31;
    if (lid == 0) sh[wid] = m;
    __syncthreads();
    if (wid == 0){
        float a = (lid < 8) ? sh[lid] : -1e30f;
        a = warpMax(a);
        if (lid == 0) sh[0] = a;
    }
    __syncthreads();
    m = sh[0];
    float s = 0.f;
    for (int k = tid; k < len; k += 256){ float e = expf(tmp[k] - m); tmp[k] = e; s += e; }
    s = warpSum(s);
    if (lid == 0) sh[wid + 8] = s;
    __syncthreads();
    if (wid == 0){
        float a = (lid < 8) ? sh[lid + 8] : 0.f;
        a = warpSum(a);
        if (lid == 0) sh[1] = a;
    }
    __syncthreads();
    float inv = 1.0f / sh[1];
    for (int k = tid; k < SS; k += 256)
        row[k] = (k < len) ? tmp[k] * inv : 0.0f;
}

// ---------------- templated strided-batched SGEMM ----------------
// C = alpha*A@B (+bias) (relu) (+res).  z-batch split into (bb,hh) via batchH.
// Requires: THREADS=256, BM*BK/4==256, (TRANSB? BN*BK/4 : BK*BN/4)==256,
//           M%BM==0, N%BN==0, K%BK==0 (guaranteed by call sites).
template<int BM,int BN,int BK,int TM,int TN,bool TRANSB>
__global__ void __launch_bounds__(256)
gemm_kernel(int M, int N, int K,
            const float* __restrict__ A, int lda, long long sAb, long long sAh,
            const float* __restrict__ B, int ldb, long long sBb, long long sBh,
            float*       __restrict__ C, int ldc, long long sCb, long long sCh,
            const float* __restrict__ bias,
            const float* __restrict__ res,
            float alpha, int relu, int batchH){
    __shared__ float As[BK][BM];
    __shared__ float Bs[BK][BN];
    int z  = blockIdx.z;
    int bb = z / batchH, hh = z - bb * batchH;
    A += bb * sAb + hh * sAh;
    B += bb * sBb + hh * sBh;
    long long coff = bb * sCb + hh * sCh;
    C += coff;
    if (res) res += coff;

    const int m0 = blockIdx.y * BM, n0 = blockIdx.x * BN;
    const int tid = threadIdx.x;
    const int tm = (tid / (BN / TN)) * TM;
    const int tn = (tid % (BN / TN)) * TN;

    const int arow = tid / (BK / 4);
    const int acol = (tid % (BK / 4)) * 4;
    int brow, bcol;
    if (TRANSB){ brow = tid / (BK / 4); bcol = (tid % (BK / 4)) * 4; }
    else       { brow = tid / (BN / 4); bcol = (tid % (BN / 4)) * 4; }

    float acc[TM][TN] = {};

    for (int k0 = 0; k0 < K; k0 += BK){
        float4 av = *(const float4*)(A + (long long)(m0 + arow) * lda + k0 + acol);
        As[acol + 0][arow] = av.x;
        As[acol + 1][arow] = av.y;
        As[acol + 2][arow] = av.z;
        As[acol + 3][arow] = av.w;
        if (TRANSB){
            float4 bv = *(const float4*)(B + (long long)(n0 + brow) * ldb + k0 + bcol);
            Bs[bcol + 0][brow] = bv.x;
            Bs[bcol + 1][brow] = bv.y;
            Bs[bcol + 2][brow] = bv.z;
            Bs[bcol + 3][brow] = bv.w;
        } else {
            float4 bv = *(const float4*)(B + (long long)(k0 + brow) * ldb + n0 + bcol);
            *(float4*)&Bs[brow][bcol] = bv;
        }
        __syncthreads();
#pragma unroll
        for (int kk = 0; kk < BK; kk++){
            float ar[TM], br[TN];
#pragma unroll
            for (int i = 0; i < TM; i++) ar[i] = As[kk][tm + i];
#pragma unroll
            for (int j = 0; j < TN; j++) br[j] = Bs[kk][tn + j];
#pragma unroll
            for (int i = 0; i < TM; i++)
#pragma unroll
                for (int j = 0; j < TN; j++)
                    acc[i][j] += ar[i] * br[j];
        }
        __syncthreads();
    }

#pragma unroll
    for (int i = 0; i < TM; i++){
        int r = m0 + tm + i;
#pragma unroll
        for (int j = 0; j < TN; j++){
            int c = n0 + tn + j;
            float v = acc[i][j] * alpha;
            if (bias) v += bias[c];
            if (relu) v = fmaxf(v, 0.0f);
            if (res)  v += res[(long long)r * ldc + c];
            C[(long long)r * ldc + c] = v;
        }
    }
}

// ---------------- host-side helpers ----------------
static void big_gemm(const float* A, int lda, const float* B, int ldb,
                     float* C, int ldc, const float* bias, const float* res,
                     int M, int N, int K, float alpha, int relu){
    dim3 grid(N / 128, M / 128, 1);
    gemm_kernel<128,128,8,8,8,false><<<grid, 256>>>(
        M, N, K,
        A, lda, 0, 0,
        B, ldb, 0, 0,
        C, ldc, 0, 0,
        bias, res, alpha, relu, 1);
}

extern "C" void kernel_launch(void* const* d_in, const int* in_sizes, int n_in,
                              void* d_out, int out_size){
    const int*   tokens    = (const int*)  d_in[0];
    const int*   lengths   = (const int*)  d_in[1];
    const float* emb       = (const float*)d_in[2];
    const float* Wq        = (const float*)d_in[3];
    const float* bq        = (const float*)d_in[4];
    const float* Wkv       = (const float*)d_in[5];
    const float* bkv       = (const float*)d_in[6];
    const float* Wo        = (const float*)d_in[7];
    const float* bo        = (const float*)d_in[8];
    const float* ln_attn_g = (const float*)d_in[9];
    const float* ln_attn_b = (const float*)d_in[10];
    const float* W1        = (const float*)d_in[11];
    const float* b1        = (const float*)d_in[12];
    const float* W2        = (const float*)d_in[13];
    const float* b2        = (const float*)d_in[14];
    const float* ln_ffn_g  = (const float*)d_in[15];
    const float* ln_ffn_b  = (const float*)d_in[16];
    const float* ln_f_g    = (const float*)d_in[17];
    const float* ln_f_b    = (const float*)d_in[18];
    float* out = (float*)d_out;

    float *xb, *hb, *qb, *kvb, *ob, *fb, *scb, *peb;
    cudaGetSymbolAddress((void**)&xb,  g_x);
    cudaGetSymbolAddress((void**)&hb,  g_h);
    cudaGetSymbolAddress((void**)&qb,  g_q);
    cudaGetSymbolAddress((void**)&kvb, g_kv);
    cudaGetSymbolAddress((void**)&ob,  g_o);
    cudaGetSymbolAddress((void**)&fb,  g_ffn);
    cudaGetSymbolAddress((void**)&scb, g_sc);
    cudaGetSymbolAddress((void**)&peb, g_pe);

    pe_kernel<<<(SS*DD + 255)/256, 256>>>(peb);
    embed_kernel<<<(NTOK*DD)/256, 256>>>(tokens, emb, peb, xb);

    const long long SC_Z = (long long)SS * SS;      // per (b,h) score tile
    for (int l = 0; l < LL; l++){
        // ---- attention sublayer ----
        ln_kernel<<<NTOK, 256>>>(xb, ln_attn_g + l*DD, ln_attn_b + l*DD, hb);
        big_gemm(hb, DD, Wq  + (long long)l*DD*DD,     DD,   qb,  DD,   bq  + l*DD,   nullptr, NTOK, DD,   DD, 1.f, 0);
        big_gemm(hb, DD, Wkv + (long long)l*DD*2*DD,   2*DD, kvb, 2*DD, bkv + l*2*DD, nullptr, NTOK, 2*DD, DD, 1.f, 0);

        // scores[z,q,k] = 0.125 * Q_z @ K_z^T    (z = b*H + h)
        gemm_kernel<64,64,16,4,4,true><<<dim3(SS/64, SS/64, BB*HH), 256>>>(
            SS, SS, DQ,
            qb,  DD,   (long long)SS*DD,   64,
            kvb, 2*DD, (long long)SS*2*DD, 64,
            scb, SS,   (long long)HH*SC_Z, SC_Z,
            nullptr, nullptr, 0.125f, 0, HH);

        softmax_kernel<<<dim3(SS, BB*HH), 256>>>(scb, lengths);

        // o[z] = A_z @ V_z
        gemm_kernel<64,64,16,4,4,false><<<dim3(1, SS/64, BB*HH), 256>>>(
            SS, DV, SS,
            scb,            SS,   (long long)HH*SC_Z, SC_Z,
            kvb + HH*DQ,    2*DD, (long long)SS*2*DD, 64,
            ob,             DD,   (long long)SS*DD,   64,
            nullptr, nullptr, 1.f, 0, HH);

        // x = x + o @ Wo + bo
        big_gemm(ob, DD, Wo + (long long)l*DD*DD, DD, xb, DD, bo + l*DD, xb, NTOK, DD, DD, 1.f, 0);

        // ---- FFN sublayer ----
        ln_kernel<<<NTOK, 256>>>(xb, ln_ffn_g + l*DD, ln_ffn_b + l*DD, hb);
        big_gemm(hb, DD, W1 + (long long)l*DD*DI, DI, fb, DI, b1 + l*DI, nullptr, NTOK, DI, DD, 1.f, 1);
        big_gemm(fb, DI, W2 + (long long)l*DI*DD, DD, xb, DD, b2 + l*DD, xb,      NTOK, DD, DI, 1.f, 0);
    }

    ln_kernel<<<NTOK, 256>>>(xb, ln_f_g, ln_f_b, out);
}

// round 7
// speedup vs baseline: 2.9232x; 2.9232x over previous
#include <cuda_runtime.h>
#include <math.h>
#include <stdint.h>

#define BB 8
#define SS 512
#define DD 1024
#define HH 16
#define DQh 64
#define DI 4096
#define LL 6
#define NTOK (BB*SS)
#define EPSLN 1e-5f

// ---------------- device scratch ----------------
__device__ __align__(16) float g_x  [NTOK*DD];
__device__ __align__(16) float g_h  [NTOK*DD];
__device__ __align__(16) float g_q  [NTOK*DD];
__device__ __align__(16) float g_kv [NTOK*2*DD];
__device__ __align__(16) float g_o  [NTOK*DD];
__device__ __align__(16) float g_ffn[NTOK*DI];
__device__ __align__(16) float g_sc [BB*HH*SS*SS];
__device__ __align__(16) float g_pe [SS*DD];
__device__ __align__(16) float g_vt [BB*HH*DQh*SS];   // V transposed per (b,h): [64][512]
__device__ __align__(16) float g_wq [DD*DD];          // transposed weights [N][K]
__device__ __align__(16) float g_wkv[2*DD*DD];
__device__ __align__(16) float g_wo [DD*DD];
__device__ __align__(16) float g_w1 [DI*DD];
__device__ __align__(16) float g_w2 [DD*DI];

// ---------------- helpers ----------------
__device__ __forceinline__ float warpSum(float v){
#pragma unroll
    for (int o = 16; o; o >>= 1) v += __shfl_xor_sync(0xffffffffu, v, o);
    return v;
}
__device__ __forceinline__ float warpMax(float v){
#pragma unroll
    for (int o = 16; o; o >>= 1) v = fmaxf(v, __shfl_xor_sync(0xffffffffu, v, o));
    return v;
}
__device__ __forceinline__ float cvt_tf32(float x){
    uint32_t u;
    asm("cvt.rna.tf32.f32 %0, %1;" : "=r"(u) : "f"(x));
    return __uint_as_float(u);
}
__device__ __forceinline__ void mma8(float* c, const uint32_t* a, uint32_t b0, uint32_t b1){
    asm volatile("mma.sync.aligned.m16n8k8.row.col.f32.tf32.tf32.f32 "
        "{%0,%1,%2,%3}, {%4,%5,%6,%7}, {%8,%9}, {%0,%1,%2,%3};"
        : "+f"(c[0]), "+f"(c[1]), "+f"(c[2]), "+f"(c[3])
        : "r"(a[0]), "r"(a[1]), "r"(a[2]), "r"(a[3]), "r"(b0), "r"(b1));
}

// ---------------- positional encoding ----------------
__global__ void pe_kernel(float* __restrict__ pe){
    int idx = blockIdx.x * 256 + threadIdx.x;
    if (idx >= SS*DD) return;
    int s = idx / DD, d = idx % DD;
    double expo  = (double)(2 * (d / 2)) / (double)DD;
    double denom = pow(10000.0, expo);
    double ang   = (double)s / denom;
    pe[idx] = (float)((d % 2 == 0) ? sin(ang) : cos(ang));
}

__global__ void embed_kernel(const int* __restrict__ tokens,
                             const float* __restrict__ emb,
                             const float* __restrict__ pe,
                             float* __restrict__ x){
    int idx = blockIdx.x * 256 + threadIdx.x;
    int row = idx / DD, d = idx % DD;
    int s = row % SS;
    int t = tokens[row];
    x[idx] = emb[(long long)t * DD + d] * 32.0f + pe[s * DD + d];
}

// ---------------- layernorm ----------------
__global__ void ln_kernel(const float* __restrict__ x,
                          const float* __restrict__ g,
                          const float* __restrict__ be,
                          float* __restrict__ y){
    int row = blockIdx.x, tid = threadIdx.x;
    const float4* xr = (const float4*)(x + (long long)row * DD);
    float4 v = xr[tid];
    float s  = v.x + v.y + v.z + v.w;
    float sq = v.x*v.x + v.y*v.y + v.z*v.z + v.w*v.w;
    __shared__ float sh[16];
    s  = warpSum(s);
    sq = warpSum(sq);
    int wid = tid >> 5, lid = tid & 31;
    if (lid == 0){ sh[wid] = s; sh[wid + 8] = sq; }
    __syncthreads();
    if (wid == 0){
        float a  = (lid < 8) ? sh[lid]     : 0.f;
        float b2 = (lid < 8) ? sh[lid + 8] : 0.f;
        a  = warpSum(a);
        b2 = warpSum(b2);
        if (lid == 0){ sh[0] = a; sh[1] = b2; }
    }
    __syncthreads();
    float mean = sh[0] * (1.0f / DD);
    float var  = sh[1] * (1.0f / DD) - mean * mean;
    float rstd = rsqrtf(var + EPSLN);
    float4 gv = ((const float4*)g)[tid];
    float4 bv = ((const float4*)be)[tid];
    float4 o;
    o.x = (v.x - mean) * rstd * gv.x + bv.x;
    o.y = (v.y - mean) * rstd * gv.y + bv.y;
    o.z = (v.z - mean) * rstd * gv.z + bv.z;
    o.w = (v.w - mean) * rstd * gv.w + bv.w;
    ((float4*)(y + (long long)row * DD))[tid] = o;
}

// ---------------- masked softmax ----------------
__global__ void softmax_kernel(float* __restrict__ sc, const int* __restrict__ lengths){
    int z = blockIdx.y;
    int q = blockIdx.x;
    int b = z >> 4;
    int len = lengths[b];
    float* row = sc + (((long long)z << 9) + q) * SS;
    int tid = threadIdx.x;
    __shared__ float tmp[SS];
    __shared__ float sh[16];
    float m = -1e30f;
    for (int k = tid; k < len; k += 256){ float v = row[k]; tmp[k] = v; m = fmaxf(m, v); }
    m = warpMax(m);
    int wid = tid >> 5, lid = tid & 31;
    if (lid == 0) sh[wid] = m;
    __syncthreads();
    if (wid == 0){
        float a = (lid < 8) ? sh[lid] : -1e30f;
        a = warpMax(a);
        if (lid == 0) sh[0] = a;
    }
    __syncthreads();
    m = sh[0];
    float s = 0.f;
    for (int k = tid; k < len; k += 256){ float e = expf(tmp[k] - m); tmp[k] = e; s += e; }
    s = warpSum(s);
    if (lid == 0) sh[wid + 8] = s;
    __syncthreads();
    if (wid == 0){
        float a = (lid < 8) ? sh[lid + 8] : 0.f;
        a = warpSum(a);
        if (lid == 0) sh[1] = a;
    }
    __syncthreads();
    float inv = 1.0f / sh[1];
    for (int k = tid; k < SS; k += 256)
        row[k] = (k < len) ? tmp[k] * inv : 0.0f;
}

// ---------------- transpose: dst[c][r] = src[r][c] ----------------
__global__ void transpose_kernel(const float* __restrict__ src, float* __restrict__ dst,
                                 int R, int C){
    __shared__ float t[32][33];
    int c0 = blockIdx.x * 32, r0 = blockIdx.y * 32;
    int x = threadIdx.x, y = threadIdx.y;
#pragma unroll
    for (int j = 0; j < 4; j++)
        t[y + j*8][x] = src[(long long)(r0 + y + j*8) * C + c0 + x];
    __syncthreads();
#pragma unroll
    for (int j = 0; j < 4; j++)
        dst[(long long)(c0 + y + j*8) * R + r0 + x] = t[x][y + j*8];
}

// V transpose: vt[z][d][t] = kv[b*512+t][1024 + h*64 + d], z = b*16+h
__global__ void vtrans_kernel(const float* __restrict__ kv, float* __restrict__ vt){
    __shared__ float t[32][33];
    int z = blockIdx.z;
    int b = z >> 4, h = z & 15;
    int d0 = blockIdx.x * 32, t0 = blockIdx.y * 32;
    const float* src = kv + (long long)b * 512 * 2048 + 1024 + h * 64;
    float* dst = vt + (long long)z * 64 * 512;
    int x = threadIdx.x, y = threadIdx.y;
#pragma unroll
    for (int j = 0; j < 4; j++)
        t[y + j*8][x] = src[(long long)(t0 + y + j*8) * 2048 + d0 + x];
    __syncthreads();
#pragma unroll
    for (int j = 0; j < 4; j++)
        dst[(long long)(d0 + y + j*8) * 512 + t0 + x] = t[x][y + j*8];
}

// ---------------- tf32 mma.sync batched GEMM ----------------
// C[m][n] = alpha * sum_k A[m][k]*B[n][k] (+bias)(relu)(+res)
template<int BN>
__global__ void __launch_bounds__(256, 2)
mma_gemm(int K,
         const float* __restrict__ A, int lda, long long sAb, long long sAh,
         const float* __restrict__ B, int ldb, long long sBb, long long sBh,
         float*       __restrict__ C, int ldc, long long sCb, long long sCh,
         const float* __restrict__ bias, const float* __restrict__ res,
         float alpha, int relu, int batchH)
{
    constexpr int BM  = 128;
    constexpr int BKP = 36;
    constexpr int NF  = BN / 16;
    constexpr int NBI = BN / 32;

    __shared__ float As[BM * BKP];
    __shared__ float Bs[BN * BKP];

    const int tid = threadIdx.x;
    const int wid = tid >> 5, lid = tid & 31;
    const int wm = wid >> 1, wn = wid & 1;
    const int tg = lid >> 2, tig = lid & 3;

    int z  = blockIdx.z;
    int bb = z / batchH, hh = z - bb * batchH;
    A += bb * sAb + hh * sAh;
    B += bb * sBb + hh * sBh;
    long long coff = bb * sCb + hh * sCh;

    const int m0 = blockIdx.y * BM;
    const int n0 = blockIdx.x * BN;

    float acc[2][NF][4];
#pragma unroll
    for (int i = 0; i < 2; i++)
#pragma unroll
        for (int j = 0; j < NF; j++)
#pragma unroll
            for (int q = 0; q < 4; q++) acc[i][j][q] = 0.f;

    float4 ar[4], br[NBI];

    {
        const int k0 = 0;
#pragma unroll
        for (int i = 0; i < 4; i++){
            int idx = i * 256 + tid;
            int row = idx >> 3, c4 = idx & 7;
            ar[i] = *(const float4*)(A + (long long)(m0 + row) * lda + k0 + c4 * 4);
        }
#pragma unroll
        for (int i = 0; i < NBI; i++){
            int idx = i * 256 + tid;
            int row = idx >> 3, c4 = idx & 7;
            br[i] = *(const float4*)(B + (long long)(n0 + row) * ldb + k0 + c4 * 4);
        }
    }

    const int nst = K >> 5;
    for (int s = 0; s < nst; s++){
        __syncthreads();
#pragma unroll
        for (int i = 0; i < 4; i++){
            int idx = i * 256 + tid;
            int row = idx >> 3, c4 = idx & 7;
            float* p = As + row * BKP + c4 * 4;
            p[0] = cvt_tf32(ar[i].x); p[1] = cvt_tf32(ar[i].y);
            p[2] = cvt_tf32(ar[i].z); p[3] = cvt_tf32(ar[i].w);
        }
#pragma unroll
        for (int i = 0; i < NBI; i++){
            int idx = i * 256 + tid;
            int row = idx >> 3, c4 = idx & 7;
            float* p = Bs + row * BKP + c4 * 4;
            p[0] = cvt_tf32(br[i].x); p[1] = cvt_tf32(br[i].y);
            p[2] = cvt_tf32(br[i].z); p[3] = cvt_tf32(br[i].w);
        }
        __syncthreads();

        if (s + 1 < nst){
            const int k0 = (s + 1) << 5;
#pragma unroll
            for (int i = 0; i < 4; i++){
                int idx = i * 256 + tid;
                int row = idx >> 3, c4 = idx & 7;
                ar[i] = *(const float4*)(A + (long long)(m0 + row) * lda + k0 + c4 * 4);
            }
#pragma unroll
            for (int i = 0; i < NBI; i++){
                int idx = i * 256 + tid;
                int row = idx >> 3, c4 = idx & 7;
                br[i] = *(const float4*)(B + (long long)(n0 + row) * ldb + k0 + c4 * 4);
            }
        }

#pragma unroll
        for (int k8 = 0; k8 < 4; k8++){
            const int ko = k8 * 8;
            uint32_t af[2][4];
#pragma unroll
            for (int mi = 0; mi < 2; mi++){
                const float* ap = As + (wm * 32 + mi * 16 + tg) * BKP + ko + tig;
                af[mi][0] = __float_as_uint(ap[0]);
                af[mi][1] = __float_as_uint(ap[8 * BKP]);
                af[mi][2] = __float_as_uint(ap[4]);
                af[mi][3] = __float_as_uint(ap[8 * BKP + 4]);
            }
#pragma unroll
            for (int ni = 0; ni < NF; ni++){
                const float* bp = Bs + (wn * (BN/2) + ni * 8 + tg) * BKP + ko + tig;
                uint32_t b0 = __float_as_uint(bp[0]);
                uint32_t b1 = __float_as_uint(bp[4]);
#pragma unroll
                for (int mi = 0; mi < 2; mi++)
                    mma8(acc[mi][ni], af[mi], b0, b1);
            }
        }
    }

    float* Cp = C + coff;
    const float* Rp = res ? res + coff : nullptr;
#pragma unroll
    for (int mi = 0; mi < 2; mi++){
        int r0 = m0 + wm * 32 + mi * 16 + tg;
#pragma unroll
        for (int ni = 0; ni < NF; ni++){
            int cc = n0 + wn * (BN/2) + ni * 8 + tig * 2;
            float bx = 0.f, by = 0.f;
            if (bias){ bx = bias[cc]; by = bias[cc + 1]; }
#pragma unroll
            for (int hrow = 0; hrow < 2; hrow++){
                int r = r0 + hrow * 8;
                float v0 = acc[mi][ni][hrow * 2 + 0] * alpha + bx;
                float v1 = acc[mi][ni][hrow * 2 + 1] * alpha + by;
                if (relu){ v0 = fmaxf(v0, 0.f); v1 = fmaxf(v1, 0.f); }
                long long g = (long long)r * ldc + cc;
                if (Rp){
                    float2 rv = *(const float2*)(Rp + g);
                    v0 += rv.x; v1 += rv.y;
                }
                float2 o; o.x = v0; o.y = v1;
                *(float2*)(Cp + g) = o;
            }
        }
    }
}

// ---------------- host side ----------------
static void big_gemm(const float* A, int lda, const float* Bt, int ldb,
                     float* C, int ldc, const float* bias, const float* res,
                     int M, int N, int K, int relu = 0){
    dim3 grid(N / 128, M / 128, 1);
    mma_gemm<128><<<grid, 256>>>(
        K, A, lda, 0, 0, Bt, ldb, 0, 0, C, ldc, 0, 0,
        bias, res, 1.0f, relu, 1);
}

extern "C" void kernel_launch(void* const* d_in, const int* in_sizes, int n_in,
                              void* d_out, int out_size){
    const int*   tokens    = (const int*)  d_in[0];
    const int*   lengths   = (const int*)  d_in[1];
    const float* emb       = (const float*)d_in[2];
    const float* Wq        = (const float*)d_in[3];
    const float* bq        = (const float*)d_in[4];
    const float* Wkv       = (const float*)d_in[5];
    const float* bkv       = (const float*)d_in[6];
    const float* Wo        = (const float*)d_in[7];
    const float* bo        = (const float*)d_in[8];
    const float* ln_attn_g = (const float*)d_in[9];
    const float* ln_attn_b = (const float*)d_in[10];
    const float* W1        = (const float*)d_in[11];
    const float* b1        = (const float*)d_in[12];
    const float* W2        = (const float*)d_in[13];
    const float* b2        = (const float*)d_in[14];
    const float* ln_ffn_g  = (const float*)d_in[15];
    const float* ln_ffn_b  = (const float*)d_in[16];
    const float* ln_f_g    = (const float*)d_in[17];
    const float* ln_f_b    = (const float*)d_in[18];
    float* out = (float*)d_out;

    float *xb, *hb, *qb, *kvb, *ob, *fb, *scb, *peb, *vtb;
    float *wqt, *wkvt, *wot, *w1t, *w2t;
    cudaGetSymbolAddress((void**)&xb,   g_x);
    cudaGetSymbolAddress((void**)&hb,   g_h);
    cudaGetSymbolAddress((void**)&qb,   g_q);
    cudaGetSymbolAddress((void**)&kvb,  g_kv);
    cudaGetSymbolAddress((void**)&ob,   g_o);
    cudaGetSymbolAddress((void**)&fb,   g_ffn);
    cudaGetSymbolAddress((void**)&scb,  g_sc);
    cudaGetSymbolAddress((void**)&peb,  g_pe);
    cudaGetSymbolAddress((void**)&vtb,  g_vt);
    cudaGetSymbolAddress((void**)&wqt,  g_wq);
    cudaGetSymbolAddress((void**)&wkvt, g_wkv);
    cudaGetSymbolAddress((void**)&wot,  g_wo);
    cudaGetSymbolAddress((void**)&w1t,  g_w1);
    cudaGetSymbolAddress((void**)&w2t,  g_w2);

    pe_kernel<<<(SS*DD + 255)/256, 256>>>(peb);
    embed_kernel<<<(NTOK*DD)/256, 256>>>(tokens, emb, peb, xb);

    dim3 tb(32, 8);
    const long long SC_Z = (long long)SS * SS;
    for (int l = 0; l < LL; l++){
        // ---- attention sublayer ----
        ln_kernel<<<NTOK, 256>>>(xb, ln_attn_g + l*DD, ln_attn_b + l*DD, hb);

        transpose_kernel<<<dim3(DD/32,   DD/32), tb>>>(Wq  + (long long)l*DD*DD,   wqt,  DD, DD);
        transpose_kernel<<<dim3(2*DD/32, DD/32), tb>>>(Wkv + (long long)l*DD*2*DD, wkvt, DD, 2*DD);

        big_gemm(hb, DD, wqt,  DD, qb,  DD,   bq  + l*DD,   nullptr, NTOK, DD,   DD);
        big_gemm(hb, DD, wkvt, DD, kvb, 2*DD, bkv + l*2*DD, nullptr, NTOK, 2*DD, DD);

        // scores[z,q,k] = 0.125 * Q_z @ K_z^T
        mma_gemm<128><<<dim3(SS/128, SS/128, BB*HH), 256>>>(
            64,
            qb,  DD,   (long long)SS*DD,   64,
            kvb, 2*DD, (long long)SS*2*DD, 64,
            scb, SS,   (long long)HH*SC_Z, SC_Z,
            nullptr, nullptr, 0.125f, 0, HH);

        softmax_kernel<<<dim3(SS, BB*HH), 256>>>(scb, lengths);

        // V transpose then o[z] = P_z @ V_z
        vtrans_kernel<<<dim3(2, 16, BB*HH), tb>>>(kvb, vtb);
        mma_gemm<64><<<dim3(1, SS/128, BB*HH), 256>>>(
            SS,
            scb, SS,  (long long)HH*SC_Z,          SC_Z,
            vtb, SS,  (long long)HH*DQh*SS,        (long long)DQh*SS,
            ob,  DD,  (long long)SS*DD,            DQh,
            nullptr, nullptr, 1.0f, 0, HH);

        // x = x + o @ Wo + bo
        transpose_kernel<<<dim3(DD/32, DD/32), tb>>>(Wo + (long long)l*DD*DD, wot, DD, DD);
        big_gemm(ob, DD, wot, DD, xb, DD, bo + l*DD, xb, NTOK, DD, DD);

        // ---- FFN sublayer ----
        ln_kernel<<<NTOK, 256>>>(xb, ln_ffn_g + l*DD, ln_ffn_b + l*DD, hb);
        transpose_kernel<<<dim3(DI/32, DD/32), tb>>>(W1 + (long long)l*DD*DI, w1t, DD, DI);
        big_gemm(hb, DD, w1t, DD, fb, DI, b1 + l*DI, nullptr, NTOK, DI, DD, 1);
        transpose_kernel<<<dim3(DD/32, DI/32), tb>>>(W2 + (long long)l*DI*DD, w2t, DI, DD);
        big_gemm(fb, DI, w2t, DI, xb, DD, b2 + l*DD, xb, NTOK, DD, DI);
    }

    ln_kernel<<<NTOK, 256>>>(xb, ln_f_g, ln_f_b, out);
}

// round 8
// speedup vs baseline: 3.0183x; 1.0325x over previous
#include <cuda_runtime.h>
#include <math.h>
#include <stdint.h>

#define BB 8
#define SS 512
#define DD 1024
#define HH 16
#define DQh 64
#define DI 4096
#define LL 6
#define NTOK (BB*SS)
#define EPSLN 1e-5f

// ---------------- device scratch ----------------
__device__ __align__(16) float g_x  [NTOK*DD];
__device__ __align__(16) float g_h  [NTOK*DD];
__device__ __align__(16) float g_q  [NTOK*DD];
__device__ __align__(16) float g_kv [NTOK*2*DD];
__device__ __align__(16) float g_o  [NTOK*DD];
__device__ __align__(16) float g_ffn[NTOK*DI];
__device__ __align__(16) float g_sc [BB*HH*SS*SS];
__device__ __align__(16) float g_pe [SS*DD];
__device__ __align__(16) float g_vt [BB*HH*DQh*SS];
__device__ __align__(16) float g_wq [DD*DD];
__device__ __align__(16) float g_wkv[2*DD*DD];
__device__ __align__(16) float g_wo [DD*DD];
__device__ __align__(16) float g_w1 [DI*DD];
__device__ __align__(16) float g_w2 [DD*DI];

// ---------------- helpers ----------------
__device__ __forceinline__ float warpSum(float v){
#pragma unroll
    for (int o = 16; o; o >>= 1) v += __shfl_xor_sync(0xffffffffu, v, o);
    return v;
}
__device__ __forceinline__ float warpMax(float v){
#pragma unroll
    for (int o = 16; o; o >>= 1) v = fmaxf(v, __shfl_xor_sync(0xffffffffu, v, o));
    return v;
}
__device__ __forceinline__ float cvt_tf32(float x){
    uint32_t u;
    asm("cvt.rna.tf32.f32 %0, %1;" : "=r"(u) : "f"(x));
    return __uint_as_float(u);
}
__device__ __forceinline__ uint32_t smem_u32(const void* p){
    uint32_t a;
    asm("{ .reg .u64 t; cvta.to.shared.u64 t, %1; cvt.u32.u64 %0, t; }" : "=r"(a) : "l"(p));
    return a;
}
__device__ __forceinline__ void cp16(uint32_t s, const void* g){
    asm volatile("cp.async.cg.shared.global [%0], [%1], 16;" :: "r"(s), "l"(g));
}
__device__ __forceinline__ void cp_commit(){
    asm volatile("cp.async.commit_group;" ::: "memory");
}
__device__ __forceinline__ void cp_wait1(){
    asm volatile("cp.async.wait_group 1;" ::: "memory");
}
__device__ __forceinline__ void cp_wait0(){
    asm volatile("cp.async.wait_group 0;" ::: "memory");
}
__device__ __forceinline__ void mma8(float* c, const uint32_t* a, uint32_t b0, uint32_t b1){
    asm volatile("mma.sync.aligned.m16n8k8.row.col.f32.tf32.tf32.f32 "
        "{%0,%1,%2,%3}, {%4,%5,%6,%7}, {%8,%9}, {%0,%1,%2,%3};"
        : "+f"(c[0]), "+f"(c[1]), "+f"(c[2]), "+f"(c[3])
        : "r"(a[0]), "r"(a[1]), "r"(a[2]), "r"(a[3]), "r"(b0), "r"(b1));
}

// ---------------- positional encoding ----------------
__global__ void pe_kernel(float* __restrict__ pe){
    int idx = blockIdx.x * 256 + threadIdx.x;
    if (idx >= SS*DD) return;
    int s = idx / DD, d = idx % DD;
    double expo  = (double)(2 * (d / 2)) / (double)DD;
    double denom = pow(10000.0, expo);
    double ang   = (double)s / denom;
    pe[idx] = (float)((d % 2 == 0) ? sin(ang) : cos(ang));
}

__global__ void embed_kernel(const int* __restrict__ tokens,
                             const float* __restrict__ emb,
                             const float* __restrict__ pe,
                             float* __restrict__ x){
    int idx = blockIdx.x * 256 + threadIdx.x;
    int row = idx / DD, d = idx % DD;
    int s = row % SS;
    int t = tokens[row];
    x[idx] = emb[(long long)t * DD + d] * 32.0f + pe[s * DD + d];
}

// ---------------- layernorm (rnd=1: round output to tf32) ----------------
__global__ void ln_kernel(const float* __restrict__ x,
                          const float* __restrict__ g,
                          const float* __restrict__ be,
                          float* __restrict__ y, int rnd){
    int row = blockIdx.x, tid = threadIdx.x;
    const float4* xr = (const float4*)(x + (long long)row * DD);
    float4 v = xr[tid];
    float s  = v.x + v.y + v.z + v.w;
    float sq = v.x*v.x + v.y*v.y + v.z*v.z + v.w*v.w;
    __shared__ float sh[16];
    s  = warpSum(s);
    sq = warpSum(sq);
    int wid = tid >> 5, lid = tid & 31;
    if (lid == 0){ sh[wid] = s; sh[wid + 8] = sq; }
    __syncthreads();
    if (wid == 0){
        float a  = (lid < 8) ? sh[lid]     : 0.f;
        float b2 = (lid < 8) ? sh[lid + 8] : 0.f;
        a  = warpSum(a);
        b2 = warpSum(b2);
        if (lid == 0){ sh[0] = a; sh[1] = b2; }
    }
    __syncthreads();
    float mean = sh[0] * (1.0f / DD);
    float var  = sh[1] * (1.0f / DD) - mean * mean;
    float rstd = rsqrtf(var + EPSLN);
    float4 gv = ((const float4*)g)[tid];
    float4 bv = ((const float4*)be)[tid];
    float4 o;
    o.x = (v.x - mean) * rstd * gv.x + bv.x;
    o.y = (v.y - mean) * rstd * gv.y + bv.y;
    o.z = (v.z - mean) * rstd * gv.z + bv.z;
    o.w = (v.w - mean) * rstd * gv.w + bv.w;
    if (rnd){
        o.x = cvt_tf32(o.x); o.y = cvt_tf32(o.y);
        o.z = cvt_tf32(o.z); o.w = cvt_tf32(o.w);
    }
    ((float4*)(y + (long long)row * DD))[tid] = o;
}

// ---------------- masked softmax (writes tf32-rounded probabilities) ----------------
__global__ void softmax_kernel(float* __restrict__ sc, const int* __restrict__ lengths){
    int z = blockIdx.y;
    int q = blockIdx.x;
    int b = z >> 4;
    int len = lengths[b];
    float* row = sc + (((long long)z << 9) + q) * SS;
    int tid = threadIdx.x;
    __shared__ float tmp[SS];
    __shared__ float sh[16];
    float m = -1e30f;
    for (int k = tid; k < len; k += 256){ float v = row[k]; tmp[k] = v; m = fmaxf(m, v); }
    m = warpMax(m);
    int wid = tid >> 5, lid = tid & 31;
    if (lid == 0) sh[wid] = m;
    __syncthreads();
    if (wid == 0){
        float a = (lid < 8) ? sh[lid] : -1e30f;
        a = warpMax(a);
        if (lid == 0) sh[0] = a;
    }
    __syncthreads();
    m = sh[0];
    float s = 0.f;
    for (int k = tid; k < len; k += 256){ float e = expf(tmp[k] - m); tmp[k] = e; s += e; }
    s = warpSum(s);
    if (lid == 0) sh[wid + 8] = s;
    __syncthreads();
    if (wid == 0){
        float a = (lid < 8) ? sh[lid + 8] : 0.f;
        a = warpSum(a);
        if (lid == 0) sh[1] = a;
    }
    __syncthreads();
    float inv = 1.0f / sh[1];
    for (int k = tid; k < SS; k += 256)
        row[k] = (k < len) ? cvt_tf32(tmp[k] * inv) : 0.0f;
}

// ---------------- transpose with tf32 rounding: dst[c][r] = tf32(src[r][c]) ----------------
__global__ void transpose_kernel(const float* __restrict__ src, float* __restrict__ dst,
                                 int R, int C){
    __shared__ float t[32][33];
    int c0 = blockIdx.x * 32, r0 = blockIdx.y * 32;
    int x = threadIdx.x, y = threadIdx.y;
#pragma unroll
    for (int j = 0; j < 4; j++)
        t[y + j*8][x] = cvt_tf32(src[(long long)(r0 + y + j*8) * C + c0 + x]);
    __syncthreads();
#pragma unroll
    for (int j = 0; j < 4; j++)
        dst[(long long)(c0 + y + j*8) * R + r0 + x] = t[x][y + j*8];
}

// V transpose (kv already tf32-rounded by QKV epilogue)
__global__ void vtrans_kernel(const float* __restrict__ kv, float* __restrict__ vt){
    __shared__ float t[32][33];
    int z = blockIdx.z;
    int b = z >> 4, h = z & 15;
    int d0 = blockIdx.x * 32, t0 = blockIdx.y * 32;
    const float* src = kv + (long long)b * 512 * 2048 + 1024 + h * 64;
    float* dst = vt + (long long)z * 64 * 512;
    int x = threadIdx.x, y = threadIdx.y;
#pragma unroll
    for (int j = 0; j < 4; j++)
        t[y + j*8][x] = src[(long long)(t0 + y + j*8) * 2048 + d0 + x];
    __syncthreads();
#pragma unroll
    for (int j = 0; j < 4; j++)
        dst[(long long)(d0 + y + j*8) * 512 + t0 + x] = t[x][y + j*8];
}

// ---------------- tf32 mma.sync batched GEMM, cp.async 2-stage ----------------
// C[m][n] = alpha * sum_k A[m][k]*B[n][k] (+bias)(relu)(+res)(rnd_out)
// Inputs A, B MUST be pre-rounded to tf32.
template<int BN>
__global__ void __launch_bounds__(256, 2)
mma_gemm(int K,
         const float* __restrict__ A, int lda, long long sAb, long long sAh,
         const float* __restrict__ B, int ldb, long long sBb, long long sBh,
         float*       __restrict__ C, int ldc, long long sCb, long long sCh,
         const float* __restrict__ bias, const float* __restrict__ res,
         float alpha, int relu, int rnd_out, int batchH)
{
    constexpr int BM  = 128;
    constexpr int BKP = 36;
    constexpr int NF  = BN / 16;
    constexpr int NBI = BN / 32;
    constexpr int ASZ = BM * BKP;
    constexpr int BSZ = BN * BKP;

    extern __shared__ float smp[];
    float* Asb[2] = { smp,            smp + ASZ };
    float* Bsb[2] = { smp + 2*ASZ,    smp + 2*ASZ + BSZ };
    uint32_t asu[2], bsu[2];
    asu[0] = smem_u32(Asb[0]); asu[1] = smem_u32(Asb[1]);
    bsu[0] = smem_u32(Bsb[0]); bsu[1] = smem_u32(Bsb[1]);

    const int tid = threadIdx.x;
    const int wid = tid >> 5, lid = tid & 31;
    const int wm = wid >> 1, wn = wid & 1;
    const int tg = lid >> 2, tig = lid & 3;

    int z  = blockIdx.z;
    int bb = z / batchH, hh = z - bb * batchH;
    A += bb * sAb + hh * sAh;
    B += bb * sBb + hh * sBh;
    long long coff = bb * sCb + hh * sCh;

    const int m0 = blockIdx.y * BM;
    const int n0 = blockIdx.x * BN;

    const int arow = tid >> 3, ac4 = tid & 7;   // A staging: 4 iters cover 128 rows
    const int nst = K >> 5;

    float acc[2][NF][4];
#pragma unroll
    for (int i = 0; i < 2; i++)
#pragma unroll
        for (int j = 0; j < NF; j++)
#pragma unroll
            for (int q = 0; q < 4; q++) acc[i][j][q] = 0.f;

    // stage 0
    {
        const int k0 = 0;
#pragma unroll
        for (int i = 0; i < 4; i++){
            int row = arow + i * 32;
            cp16(asu[0] + (uint32_t)(row * BKP + ac4 * 4) * 4,
                 A + (long long)(m0 + row) * lda + k0 + ac4 * 4);
        }
#pragma unroll
        for (int i = 0; i < NBI; i++){
            int row = arow + i * 32;
            cp16(bsu[0] + (uint32_t)(row * BKP + ac4 * 4) * 4,
                 B + (long long)(n0 + row) * ldb + k0 + ac4 * 4);
        }
        cp_commit();
    }

    for (int s = 0; s < nst; s++){
        const int buf = s & 1;
        if (s + 1 < nst){
            const int nb = (s + 1) & 1;
            const int k0 = (s + 1) << 5;
#pragma unroll
            for (int i = 0; i < 4; i++){
                int row = arow + i * 32;
                cp16(asu[nb] + (uint32_t)(row * BKP + ac4 * 4) * 4,
                     A + (long long)(m0 + row) * lda + k0 + ac4 * 4);
            }
#pragma unroll
            for (int i = 0; i < NBI; i++){
                int row = arow + i * 32;
                cp16(bsu[nb] + (uint32_t)(row * BKP + ac4 * 4) * 4,
                     B + (long long)(n0 + row) * ldb + k0 + ac4 * 4);
            }
            cp_commit();
            cp_wait1();
        } else {
            cp_wait0();
        }
        __syncthreads();

        const float* As = Asb[buf];
        const float* Bs = Bsb[buf];
#pragma unroll
        for (int k8 = 0; k8 < 4; k8++){
            const int ko = k8 * 8;
            uint32_t af[2][4];
#pragma unroll
            for (int mi = 0; mi < 2; mi++){
                const float* ap = As + (wm * 32 + mi * 16 + tg) * BKP + ko + tig;
                af[mi][0] = __float_as_uint(ap[0]);
                af[mi][1] = __float_as_uint(ap[8 * BKP]);
                af[mi][2] = __float_as_uint(ap[4]);
                af[mi][3] = __float_as_uint(ap[8 * BKP + 4]);
            }
#pragma unroll
            for (int ni = 0; ni < NF; ni++){
                const float* bp = Bs + (wn * (BN/2) + ni * 8 + tg) * BKP + ko + tig;
                uint32_t b0 = __float_as_uint(bp[0]);
                uint32_t b1 = __float_as_uint(bp[4]);
#pragma unroll
                for (int mi = 0; mi < 2; mi++)
                    mma8(acc[mi][ni], af[mi], b0, b1);
            }
        }
        __syncthreads();
    }

    // ---- epilogue ----
    float* Cp = C + coff;
    const float* Rp = res ? res + coff : nullptr;
#pragma unroll
    for (int mi = 0; mi < 2; mi++){
        int r0 = m0 + wm * 32 + mi * 16 + tg;
#pragma unroll
        for (int ni = 0; ni < NF; ni++){
            int cc = n0 + wn * (BN/2) + ni * 8 + tig * 2;
            float bx = 0.f, by = 0.f;
            if (bias){ bx = bias[cc]; by = bias[cc + 1]; }
#pragma unroll
            for (int hrow = 0; hrow < 2; hrow++){
                int r = r0 + hrow * 8;
                float v0 = acc[mi][ni][hrow * 2 + 0] * alpha + bx;
                float v1 = acc[mi][ni][hrow * 2 + 1] * alpha + by;
                if (relu){ v0 = fmaxf(v0, 0.f); v1 = fmaxf(v1, 0.f); }
                long long g = (long long)r * ldc + cc;
                if (Rp){
                    float2 rv = *(const float2*)(Rp + g);
                    v0 += rv.x; v1 += rv.y;
                }
                if (rnd_out){ v0 = cvt_tf32(v0); v1 = cvt_tf32(v1); }
                float2 o; o.x = v0; o.y = v1;
                *(float2*)(Cp + g) = o;
            }
        }
    }
}

// ---------------- host side ----------------
#define SM128 ((2*128*36 + 2*128*36) * 4)   // 73728
#define SM64  ((2*128*36 + 2*64*36) * 4)    // 55296

static void big_gemm(const float* A, int lda, const float* Bt, int ldb,
                     float* C, int ldc, const float* bias, const float* res,
                     int M, int N, int K, int relu, int rnd_out){
    dim3 grid(N / 128, M / 128, 1);
    mma_gemm<128><<<grid, 256, SM128>>>(
        K, A, lda, 0, 0, Bt, ldb, 0, 0, C, ldc, 0, 0,
        bias, res, 1.0f, relu, rnd_out, 1);
}

extern "C" void kernel_launch(void* const* d_in, const int* in_sizes, int n_in,
                              void* d_out, int out_size){
    const int*   tokens    = (const int*)  d_in[0];
    const int*   lengths   = (const int*)  d_in[1];
    const float* emb       = (const float*)d_in[2];
    const float* Wq        = (const float*)d_in[3];
    const float* bq        = (const float*)d_in[4];
    const float* Wkv       = (const float*)d_in[5];
    const float* bkv       = (const float*)d_in[6];
    const float* Wo        = (const float*)d_in[7];
    const float* bo        = (const float*)d_in[8];
    const float* ln_attn_g = (const float*)d_in[9];
    const float* ln_attn_b = (const float*)d_in[10];
    const float* W1        = (const float*)d_in[11];
    const float* b1        = (const float*)d_in[12];
    const float* W2        = (const float*)d_in[13];
    const float* b2        = (const float*)d_in[14];
    const float* ln_ffn_g  = (const float*)d_in[15];
    const float* ln_ffn_b  = (const float*)d_in[16];
    const float* ln_f_g    = (const float*)d_in[17];
    const float* ln_f_b    = (const float*)d_in[18];
    float* out = (float*)d_out;

    cudaFuncSetAttribute((const void*)mma_gemm<128>, cudaFuncAttributeMaxDynamicSharedMemorySize, SM128);
    cudaFuncSetAttribute((const void*)mma_gemm<64>,  cudaFuncAttributeMaxDynamicSharedMemorySize, SM64);

    float *xb, *hb, *qb, *kvb, *ob, *fb, *scb, *peb, *vtb;
    float *wqt, *wkvt, *wot, *w1t, *w2t;
    cudaGetSymbolAddress((void**)&xb,   g_x);
    cudaGetSymbolAddress((void**)&hb,   g_h);
    cudaGetSymbolAddress((void**)&qb,   g_q);
    cudaGetSymbolAddress((void**)&kvb,  g_kv);
    cudaGetSymbolAddress((void**)&ob,   g_o);
    cudaGetSymbolAddress((void**)&fb,   g_ffn);
    cudaGetSymbolAddress((void**)&scb,  g_sc);
    cudaGetSymbolAddress((void**)&peb,  g_pe);
    cudaGetSymbolAddress((void**)&vtb,  g_vt);
    cudaGetSymbolAddress((void**)&wqt,  g_wq);
    cudaGetSymbolAddress((void**)&wkvt, g_wkv);
    cudaGetSymbolAddress((void**)&wot,  g_wo);
    cudaGetSymbolAddress((void**)&w1t,  g_w1);
    cudaGetSymbolAddress((void**)&w2t,  g_w2);

    pe_kernel<<<(SS*DD + 255)/256, 256>>>(peb);
    embed_kernel<<<(NTOK*DD)/256, 256>>>(tokens, emb, peb, xb);

    dim3 tb(32, 8);
    const long long SC_Z = (long long)SS * SS;
    for (int l = 0; l < LL; l++){
        // ---- attention sublayer ----
        ln_kernel<<<NTOK, 256>>>(xb, ln_attn_g + l*DD, ln_attn_b + l*DD, hb, 1);

        transpose_kernel<<<dim3(DD/32,   DD/32), tb>>>(Wq  + (long long)l*DD*DD,   wqt,  DD, DD);
        transpose_kernel<<<dim3(2*DD/32, DD/32), tb>>>(Wkv + (long long)l*DD*2*DD, wkvt, DD, 2*DD);

        big_gemm(hb, DD, wqt,  DD, qb,  DD,   bq  + l*DD,   nullptr, NTOK, DD,   DD, 0, 1);
        big_gemm(hb, DD, wkvt, DD, kvb, 2*DD, bkv + l*2*DD, nullptr, NTOK, 2*DD, DD, 0, 1);

        // scores[z,q,k] = 0.125 * Q_z @ K_z^T
        mma_gemm<128><<<dim3(SS/128, SS/128, BB*HH), 256, SM128>>>(
            64,
            qb,  DD,   (long long)SS*DD,   64,
            kvb, 2*DD, (long long)SS*2*DD, 64,
            scb, SS,   (long long)HH*SC_Z, SC_Z,
            nullptr, nullptr, 0.125f, 0, 0, HH);

        softmax_kernel<<<dim3(SS, BB*HH), 256>>>(scb, lengths);

        // V transpose then o[z] = P_z @ V_z
        vtrans_kernel<<<dim3(2, 16, BB*HH), tb>>>(kvb, vtb);
        mma_gemm<64><<<dim3(1, SS/128, BB*HH), 256, SM64>>>(
            SS,
            scb, SS,  (long long)HH*SC_Z,   SC_Z,
            vtb, SS,  (long long)HH*DQh*SS, (long long)DQh*SS,
            ob,  DD,  (long long)SS*DD,     DQh,
            nullptr, nullptr, 1.0f, 0, 1, HH);

        // x = x + o @ Wo + bo
        transpose_kernel<<<dim3(DD/32, DD/32), tb>>>(Wo + (long long)l*DD*DD, wot, DD, DD);
        big_gemm(ob, DD, wot, DD, xb, DD, bo + l*DD, xb, NTOK, DD, DD, 0, 0);

        // ---- FFN sublayer ----
        ln_kernel<<<NTOK, 256>>>(xb, ln_ffn_g + l*DD, ln_ffn_b + l*DD, hb, 1);
        transpose_kernel<<<dim3(DI/32, DD/32), tb>>>(W1 + (long long)l*DD*DI, w1t, DD, DI);
        big_gemm(hb, DD, w1t, DD, fb, DI, b1 + l*DI, nullptr, NTOK, DI, DD, 1, 1);
        transpose_kernel<<<dim3(DD/32, DI/32), tb>>>(W2 + (long long)l*DI*DD, w2t, DI, DD);
        big_gemm(fb, DI, w2t, DI, xb, DD, b2 + l*DD, xb, NTOK, DD, DI, 0, 0);
    }

    ln_kernel<<<NTOK, 256>>>(xb, ln_f_g, ln_f_b, out, 0);
}